// round 14
// baseline (speedup 1.0000x reference)
#include <cuda_runtime.h>
#include <cuda_bf16.h>
#include <math.h>
#include <stdint.h>

#define Wn 2048
#define Cn 24
#define Vn 101
#define En 512
#define H1 1024
#define H2 1024
#define G1 3072
#define G2 3072
#define Kd 1024
#define KP 3072
#define STEPS 2048

// ---- scratch (__device__ globals; no allocations allowed) ----
__device__ float g_table[Vn * G1];
__device__ float g_h1[Wn * H1];
__device__ float g_gi2[Wn * 2 * G2];    // [word][fwd 3072 | bwd 3072]
__device__ float g_b2[2 * G2];          // [bih2f | bih2b]
__device__ float g_h2[2][2][H2];        // [dir][parity][dim]
__device__ unsigned g_bar2[2];
__device__ __nv_bfloat16 g_Ap[Wn * KP];          // [Ah | Ah | Al]
__device__ __nv_bfloat16 g_Wp1[G1 * KP];         // [Wh | Wl | Wh]
__device__ __nv_bfloat16 g_Wp2[2 * G2 * KP];     // [W2f' ; W2b']

// =================== PTX helpers ===================
__device__ __forceinline__ uint32_t smem_u32(const void* p) {
    uint32_t a;
    asm("{ .reg .u64 t; cvta.to.shared.u64 t, %1; cvt.u32.u64 %0, t; }" : "=r"(a) : "l"(p));
    return a;
}
__device__ __forceinline__ void cpasync16(uint32_t dst, const void* src) {
    asm volatile("cp.async.cg.shared.global [%0], [%1], 16;" :: "r"(dst), "l"(src));
}
#define CP_COMMIT() asm volatile("cp.async.commit_group;" ::: "memory")
#define CP_WAIT1()  asm volatile("cp.async.wait_group 1;" ::: "memory")

__device__ __forceinline__ void ldm4(uint32_t* r, uint32_t addr) {
    asm volatile("ldmatrix.sync.aligned.m8n8.x4.shared.b16 {%0,%1,%2,%3}, [%4];"
        : "=r"(r[0]), "=r"(r[1]), "=r"(r[2]), "=r"(r[3]) : "r"(addr));
}
__device__ __forceinline__ void ldm2(uint32_t* r, uint32_t addr) {
    asm volatile("ldmatrix.sync.aligned.m8n8.x2.shared.b16 {%0,%1}, [%2];"
        : "=r"(r[0]), "=r"(r[1]) : "r"(addr));
}
__device__ __forceinline__ void mma16816(float* d, const uint32_t* a, const uint32_t* b) {
    asm volatile("mma.sync.aligned.m16n8k16.row.col.f32.bf16.bf16.f32 "
        "{%0,%1,%2,%3}, {%4,%5,%6,%7}, {%8,%9}, {%0,%1,%2,%3};"
        : "+f"(d[0]), "+f"(d[1]), "+f"(d[2]), "+f"(d[3])
        : "r"(a[0]), "r"(a[1]), "r"(a[2]), "r"(a[3]), "r"(b[0]), "r"(b[1]));
}
__device__ __forceinline__ void bar_arrive_release(unsigned* p) {
    asm volatile("red.release.gpu.global.add.u32 [%0], 1;" :: "l"(p) : "memory");
}
__device__ __forceinline__ unsigned ld_acquire(const unsigned* p) {
    unsigned v;
    asm volatile("ld.acquire.gpu.global.u32 %0, [%1];" : "=r"(v) : "l"(p) : "memory");
    return v;
}
__device__ __forceinline__ float tanh_fast(float x) {
    float y;
    asm("tanh.approx.f32 %0, %1;" : "=f"(y) : "f"(x));
    return y;
}
__device__ __forceinline__ float sigmoid_fast(float x) {
    return fmaf(tanh_fast(0.5f * x), 0.5f, 0.5f);
}

// =================== plain bf16 HMMA GEMM (R13-proven; used for tail) ===================
#define STG 36864
#define HSTG 18432
#define NKIT (KP / 64)       // 48

__global__ void __launch_bounds__(256, 2) gemm_mma(
    const __nv_bfloat16* __restrict__ Ap, const __nv_bfloat16* __restrict__ Bp,
    float* __restrict__ C, const float* __restrict__ bias, int N) {
    extern __shared__ __align__(16) char smem[];
    const uint32_t sb = smem_u32(smem);
    const int tid = threadIdx.x, lane = tid & 31, warp = tid >> 5;
    const int wm = warp & 1, wn = warp >> 1;
    const int bm = blockIdx.y * 128, bn = blockIdx.x * 128;

    const int r1 = tid >> 2, c1 = tid & 3;
    const uint32_t oA = (uint32_t)r1 * 144 + (uint32_t)c1 * 16;
    const __nv_bfloat16* pa1 = Ap + (size_t)(bm + r1) * KP + c1 * 8;
    const __nv_bfloat16* pa2 = pa1 + (size_t)64 * KP;
    const __nv_bfloat16* pb1 = Bp + (size_t)(bn + r1) * KP + c1 * 8;
    const __nv_bfloat16* pb2 = pb1 + (size_t)64 * KP;

    const uint32_t aPre = (uint32_t)(wm * 64 + ((lane >> 3) & 1) * 8 + (lane & 7)) * 144
                        + (uint32_t)(lane >> 4) * 16;
    const uint32_t bPre = (uint32_t)(wn * 32 + (lane >> 4) * 8 + (lane & 7)) * 144
                        + (uint32_t)((lane >> 3) & 1) * 16;

    float acc[4][4][4];
#pragma unroll
    for (int i = 0; i < 4; i++)
#pragma unroll
        for (int j = 0; j < 4; j++)
#pragma unroll
            for (int q = 0; q < 4; q++) acc[i][j][q] = 0.f;

#define ISSUE(s, k0) do { \
    uint32_t as_ = sb + (s) * STG, bs_ = as_ + HSTG; \
    cpasync16(as_ + oA,              pa1 + (k0)); \
    cpasync16(as_ + oA + 64,         pa1 + (k0) + 32); \
    cpasync16(as_ + oA + 9216,       pa2 + (k0)); \
    cpasync16(as_ + oA + 9216 + 64,  pa2 + (k0) + 32); \
    cpasync16(bs_ + oA,              pb1 + (k0)); \
    cpasync16(bs_ + oA + 64,         pb1 + (k0) + 32); \
    cpasync16(bs_ + oA + 9216,       pb2 + (k0)); \
    cpasync16(bs_ + oA + 9216 + 64,  pb2 + (k0) + 32); \
} while (0)

    ISSUE(0, 0); CP_COMMIT();
    ISSUE(1, 64); CP_COMMIT();

    for (int it = 0; it < NKIT; it++) {
        CP_WAIT1();
        __syncthreads();
        if (it + 2 < NKIT) ISSUE((it + 2) % 3, (it + 2) * 64);
        CP_COMMIT();

        const uint32_t abase = sb + (it % 3) * STG;
        const uint32_t bbase = abase + HSTG;
#pragma unroll
        for (int ks = 0; ks < 4; ks++) {
            uint32_t a[4][4], bb[2][4];
#pragma unroll
            for (int ma = 0; ma < 4; ma++) ldm4(a[ma], abase + aPre + ma * 2304 + ks * 32);
#pragma unroll
            for (int nb = 0; nb < 2; nb++) ldm4(bb[nb], bbase + bPre + nb * 2304 + ks * 32);
#pragma unroll
            for (int ma = 0; ma < 4; ma++)
#pragma unroll
                for (int na = 0; na < 4; na++)
                    mma16816(acc[ma][na], a[ma], &bb[na >> 1][(na & 1) * 2]);
        }
    }
#undef ISSUE

    const int g = lane >> 2, t = lane & 3;
#pragma unroll
    for (int ma = 0; ma < 4; ma++) {
        int m0 = bm + wm * 64 + ma * 16 + g;
#pragma unroll
        for (int na = 0; na < 4; na++) {
            int col = bn + wn * 32 + na * 8 + t * 2;
            float b0 = bias[col], b1 = bias[col + 1];
            *(float2*)(C + (size_t)m0 * N + col) =
                make_float2(acc[ma][na][0] + b0, acc[ma][na][1] + b1);
            *(float2*)(C + (size_t)(m0 + 8) * N + col) =
                make_float2(acc[ma][na][2] + b0, acc[ma][na][3] + b1);
        }
    }
}

// =================== fused GEMM + GRU pointwise (layer-1 mainloop) ===================
// Tile: 128 words x 32 h-dims (3 gate strips of 32 B-rows). Staging 224 rows x 144B.
// 8 warps = 2(M) x 4(N): warp = 64 words x 8 dims x 3 gates.
#define FSTG 32256
#define FAB 18432            // B rows start at 128*144

__global__ void __launch_bounds__(256, 2) gemm_fused(
    const __nv_bfloat16* __restrict__ Ap, const __nv_bfloat16* __restrict__ Bp,
    const int* __restrict__ x, float* __restrict__ out,
    const float* __restrict__ bhh, int tstep) {
    extern __shared__ __align__(16) char smem[];
    const uint32_t sb = smem_u32(smem);
    const int tid = threadIdx.x, lane = tid & 31, warp = tid >> 5;
    const int wm = warp & 1, wn = warp >> 1;     // wn 0..3
    const int bm = blockIdx.y * 128, j0 = blockIdx.x * 32;

    // cp.async staging: 7 chunks/thread over 224 rows x 8 chunks
    uint32_t soff[7];
    const __nv_bfloat16* src[7];
#pragma unroll
    for (int i = 0; i < 7; i++) {
        int id = tid + i * 256;
        int row = id >> 3, ch = id & 7;
        soff[i] = (uint32_t)row * 144 + (uint32_t)ch * 16;
        if (row < 128) {
            src[i] = Ap + (size_t)(bm + row) * KP + ch * 8;
        } else {
            int r2 = row - 128, gg = r2 >> 5, dl = r2 & 31;
            src[i] = Bp + (size_t)(gg * H1 + j0 + dl) * KP + ch * 8;
        }
    }

    const uint32_t aPre = (uint32_t)(wm * 64 + ((lane >> 3) & 1) * 8 + (lane & 7)) * 144
                        + (uint32_t)(lane >> 4) * 16;
    // B ldm2 per gate strip g: rows FAB + (g*32 + wn*8 + lane&7)
    const uint32_t bPre = (uint32_t)FAB
                        + (uint32_t)(wn * 8 + (lane & 7)) * 144
                        + (uint32_t)((lane >> 3) & 1) * 16;

    float acc[4][3][4];
#pragma unroll
    for (int i = 0; i < 4; i++)
#pragma unroll
        for (int j = 0; j < 3; j++)
#pragma unroll
            for (int q = 0; q < 4; q++) acc[i][j][q] = 0.f;

#define FISSUE(s, k0) do { \
    uint32_t base_ = sb + (s) * FSTG; \
    cpasync16(base_ + soff[0], src[0] + (k0)); \
    cpasync16(base_ + soff[1], src[1] + (k0)); \
    cpasync16(base_ + soff[2], src[2] + (k0)); \
    cpasync16(base_ + soff[3], src[3] + (k0)); \
    cpasync16(base_ + soff[4], src[4] + (k0)); \
    cpasync16(base_ + soff[5], src[5] + (k0)); \
    cpasync16(base_ + soff[6], src[6] + (k0)); \
} while (0)

    FISSUE(0, 0); CP_COMMIT();
    FISSUE(1, 64); CP_COMMIT();

    for (int it = 0; it < NKIT; it++) {
        CP_WAIT1();
        __syncthreads();
        if (it + 2 < NKIT) FISSUE((it + 2) % 3, (it + 2) * 64);
        CP_COMMIT();

        const uint32_t abase = sb + (it % 3) * FSTG;
#pragma unroll
        for (int ks = 0; ks < 4; ks++) {
            uint32_t a[4][4], bb[3][2];
#pragma unroll
            for (int ma = 0; ma < 4; ma++) ldm4(a[ma], abase + aPre + ma * 2304 + ks * 32);
#pragma unroll
            for (int gg = 0; gg < 3; gg++) ldm2(bb[gg], abase + bPre + gg * 4608 + ks * 32);
#pragma unroll
            for (int ma = 0; ma < 4; ma++)
#pragma unroll
                for (int gg = 0; gg < 3; gg++)
                    mma16816(acc[ma][gg], a[ma], bb[gg]);
        }
    }
#undef FISSUE

    // ---- fused GRU epilogue ----
    const int g4 = lane >> 2, t4 = lane & 3;
    const int d = j0 + wn * 8 + t4 * 2;           // even dim index
    const float2 br = *(const float2*)(bhh + d);
    const float2 bz = *(const float2*)(bhh + H1 + d);
    const float2 bn2 = *(const float2*)(bhh + 2 * H1 + d);
    const bool last = (tstep == Cn - 1);

#pragma unroll
    for (int ma = 0; ma < 4; ma++) {
#pragma unroll
        for (int hf = 0; hf < 2; hf++) {
            const int w = bm + wm * 64 + ma * 16 + g4 + hf * 8;
            const int ch = x[w * Cn + tstep];
            const float* tb = g_table + ch * G1;
            const float2 ir = *(const float2*)(tb + d);
            const float2 iz = *(const float2*)(tb + H1 + d);
            const float2 in2 = *(const float2*)(tb + 2 * H1 + d);
            const float2 hp = *(const float2*)(g_h1 + (size_t)w * H1 + d);
            const int k0 = hf * 2;
            float r0 = sigmoid_fast(ir.x + acc[ma][0][k0 + 0] + br.x);
            float r1 = sigmoid_fast(ir.y + acc[ma][0][k0 + 1] + br.y);
            float z0 = sigmoid_fast(iz.x + acc[ma][1][k0 + 0] + bz.x);
            float z1 = sigmoid_fast(iz.y + acc[ma][1][k0 + 1] + bz.y);
            float n0 = tanh_fast(in2.x + r0 * (acc[ma][2][k0 + 0] + bn2.x));
            float n1 = tanh_fast(in2.y + r1 * (acc[ma][2][k0 + 1] + bn2.y));
            float h0 = (1.f - z0) * n0 + z0 * hp.x;
            float h1 = (1.f - z1) * n1 + z1 * hp.y;
            *(float2*)(g_h1 + (size_t)w * H1 + d) = make_float2(h0, h1);
            union { __nv_bfloat162 b; uint32_t u; } PH, PL;
            PH.b = __floats2bfloat162_rn(h0, h1);
            float l0 = h0 - __bfloat162float(__float2bfloat16(h0));
            float l1 = h1 - __bfloat162float(__float2bfloat16(h1));
            PL.b = __floats2bfloat162_rn(l0, l1);
            __nv_bfloat16* arow = g_Ap + (size_t)w * KP;
            *(uint32_t*)(arow + d) = PH.u;
            *(uint32_t*)(arow + Kd + d) = PH.u;
            *(uint32_t*)(arow + 2 * Kd + d) = PL.u;
            if (last) *(float2*)(out + (size_t)w * H1 + d) = make_float2(h0, h1);
        }
    }
}

// =================== conversions (+ per-replay init, + bias copy) ===================
__global__ void convsplit_kernel(const float* __restrict__ w,
                                 __nv_bfloat16* __restrict__ wp,
                                 const float* __restrict__ bsrc,
                                 float* __restrict__ bdst) {
    int i = blockIdx.x * 256 + threadIdx.x;
    if (i < 4 * H2) ((float*)g_h2)[i] = 0.f;
    if (i < 2) g_bar2[i] = 0u;
    if (bdst && i < G2 * 3) bdst[i] = bsrc[i];
    if (i >= G1 * Kd) return;
    int r = i >> 10, k = i & 1023;
    float v = w[i];
    __nv_bfloat16 h = __float2bfloat16(v);
    __nv_bfloat16 l = __float2bfloat16(v - __bfloat162float(h));
    __nv_bfloat16* row = wp + (size_t)r * KP;
    row[k] = h; row[Kd + k] = l; row[2 * Kd + k] = h;
}

__global__ void table_kernel(const float* __restrict__ emb,
                             const float* __restrict__ Wih1,
                             const float* __restrict__ bih1) {
    __shared__ __align__(16) float e[En];
    int v = blockIdx.y;
    int tid = threadIdx.x, warp = tid >> 5, lane = tid & 31;
    for (int i = tid; i < En; i += 256) e[i] = emb[v * En + i];
    __syncthreads();
    int rbase = blockIdx.x * 64 + warp * 8;
    for (int rr = 0; rr < 8; rr++) {
        int row = rbase + rr;
        const float4* wp = (const float4*)(Wih1 + (size_t)row * En);
        const float4* ep = (const float4*)e;
        float s = 0.f;
#pragma unroll
        for (int k = 0; k < 4; k++) {
            float4 wv = wp[lane + 32 * k];
            float4 ev = ep[lane + 32 * k];
            s += wv.x * ev.x + wv.y * ev.y + wv.z * ev.z + wv.w * ev.w;
        }
        for (int off = 16; off; off >>= 1) s += __shfl_xor_sync(0xffffffffu, s, off);
        if (lane == 0) g_table[v * G1 + row] = s + bih1[row];
    }
}

// ---- layer-1 t=0 pointwise (h0 = 0 -> gh = bhh) ----
__global__ void gru1_kernel(const int* __restrict__ x, int t,
                            const float* __restrict__ bhh) {
    const int w = blockIdx.x, tid = threadIdx.x, j = tid * 4;
    const int ch = x[w * Cn + t];
    const float* tb = g_table + ch * G1;
    float4 ir = *(const float4*)(tb + j);
    float4 iz = *(const float4*)(tb + H1 + j);
    float4 in4 = *(const float4*)(tb + 2 * H1 + j);
    float4 hr = *(const float4*)(bhh + j);
    float4 hz = *(const float4*)(bhh + H1 + j);
    float4 hg = *(const float4*)(bhh + 2 * H1 + j);
    float hn[4], hl[4];
    {
        const float irv[4] = {ir.x, ir.y, ir.z, ir.w};
        const float izv[4] = {iz.x, iz.y, iz.z, iz.w};
        const float inv[4] = {in4.x, in4.y, in4.z, in4.w};
        const float hrv[4] = {hr.x, hr.y, hr.z, hr.w};
        const float hzv[4] = {hz.x, hz.y, hz.z, hz.w};
        const float hgv[4] = {hg.x, hg.y, hg.z, hg.w};
#pragma unroll
        for (int q = 0; q < 4; q++) {
            float r = sigmoid_fast(irv[q] + hrv[q]);
            float z = sigmoid_fast(izv[q] + hzv[q]);
            float n = tanh_fast(inv[q] + r * hgv[q]);
            hn[q] = (1.f - z) * n;
        }
    }
    *(float4*)(g_h1 + (size_t)w * H1 + j) = make_float4(hn[0], hn[1], hn[2], hn[3]);
    union { __nv_bfloat162 h2[2]; uint2 u; } PH, PL;
    PH.h2[0] = __floats2bfloat162_rn(hn[0], hn[1]);
    PH.h2[1] = __floats2bfloat162_rn(hn[2], hn[3]);
#pragma unroll
    for (int q = 0; q < 4; q++) {
        __nv_bfloat16 hb = __float2bfloat16(hn[q]);
        hl[q] = hn[q] - __bfloat162float(hb);
    }
    PL.h2[0] = __floats2bfloat162_rn(hl[0], hl[1]);
    PL.h2[1] = __floats2bfloat162_rn(hl[2], hl[3]);
    __nv_bfloat16* arow = g_Ap + (size_t)w * KP;
    *(uint2*)(arow + j) = PH.u;
    *(uint2*)(arow + Kd + j) = PH.u;
    *(uint2*)(arow + 2 * Kd + j) = PL.u;
}

// ---- layer-2 persistent bi-GRU: 32 CTAs x 512 threads per dir (fan-in 32) ----
__global__ void __launch_bounds__(512, 1) layer2_kernel(
    const float* __restrict__ Whhf, const float* __restrict__ Whhb,
    const float* __restrict__ bhhf, const float* __restrict__ bhhb,
    float* __restrict__ ctx) {
    __shared__ __align__(16) float hs[1024];
    const int tid = threadIdx.x, warp = tid >> 5, lane = tid & 31;
    const int cta = blockIdx.x, dir = cta >> 5, j0 = (cta & 31) << 5;
    const float* Whh = dir ? Whhb : Whhf;
    const float* bhh = dir ? bhhb : bhhf;
    const float* GI  = g_gi2 + dir * G2;
    unsigned* barp = &g_bar2[dir];
    const int d0 = j0 + 2 * warp;     // warp 0..15 -> dims d0, d0+1

    float4 wreg[6][8];
#pragma unroll
    for (int u = 0; u < 2; u++)
#pragma unroll
        for (int gg = 0; gg < 3; gg++) {
            const float4* wp = (const float4*)(Whh + (size_t)(gg * H2 + d0 + u) * H2);
#pragma unroll
            for (int c = 0; c < 8; c++) wreg[u * 3 + gg][c] = wp[c * 32 + lane];
        }
    float bg[6];
#pragma unroll
    for (int u = 0; u < 2; u++)
#pragma unroll
        for (int gg = 0; gg < 3; gg++) bg[u * 3 + gg] = bhh[gg * H2 + d0 + u];

    for (int t = 0; t < STEPS; t++) {
        const int wd = dir ? (STEPS - 1 - t) : t;
        const float* gi = GI + (size_t)wd * (2 * G2);

        ((float2*)hs)[tid] = __ldcg(((const float2*)g_h2[dir][t & 1]) + tid);
        float giv[6];
        if (lane == 0) {
#pragma unroll
            for (int u = 0; u < 2; u++)
#pragma unroll
                for (int gg = 0; gg < 3; gg++) giv[u * 3 + gg] = gi[gg * H2 + d0 + u];
        }
        __syncthreads();

        float acc[6] = {0.f, 0.f, 0.f, 0.f, 0.f, 0.f};
#pragma unroll
        for (int c = 0; c < 8; c++) {
            float4 h4 = ((const float4*)hs)[c * 32 + lane];
#pragma unroll
            for (int rr = 0; rr < 6; rr++)
                acc[rr] += wreg[rr][c].x * h4.x + wreg[rr][c].y * h4.y
                         + wreg[rr][c].z * h4.z + wreg[rr][c].w * h4.w;
        }
#pragma unroll
        for (int off = 16; off; off >>= 1)
#pragma unroll
            for (int rr = 0; rr < 6; rr++)
                acc[rr] += __shfl_xor_sync(0xffffffffu, acc[rr], off);

        if (lane == 0) {
            float hnew[2];
#pragma unroll
            for (int u = 0; u < 2; u++) {
                float r = sigmoid_fast(giv[u * 3 + 0] + acc[u * 3 + 0] + bg[u * 3 + 0]);
                float z = sigmoid_fast(giv[u * 3 + 1] + acc[u * 3 + 1] + bg[u * 3 + 1]);
                float n = tanh_fast(giv[u * 3 + 2] + r * (acc[u * 3 + 2] + bg[u * 3 + 2]));
                hnew[u] = (1.f - z) * n + z * hs[d0 + u];
            }
            *(float2*)(ctx + (size_t)wd * (2 * H2) + dir * H2 + d0) = make_float2(hnew[0], hnew[1]);
            __stcg((float2*)&g_h2[dir][(t + 1) & 1][d0], make_float2(hnew[0], hnew[1]));
        }
        __syncthreads();

        if (tid == 0) {
            bar_arrive_release(barp);
            unsigned target = 32u * (unsigned)(t + 1);
            while (ld_acquire(barp) < target) { }
        }
        __syncthreads();
    }
}

extern "C" void kernel_launch(void* const* d_in, const int* in_sizes, int n_in,
                              void* d_out, int out_size) {
    const int*   x     = (const int*)d_in[0];
    const float* emb   = (const float*)d_in[1];
    const float* Wih1  = (const float*)d_in[2];
    const float* Whh1  = (const float*)d_in[3];
    const float* bih1  = (const float*)d_in[4];
    const float* bhh1  = (const float*)d_in[5];
    const float* Wih2f = (const float*)d_in[6];
    const float* Whh2f = (const float*)d_in[7];
    const float* bih2f = (const float*)d_in[8];
    const float* bhh2f = (const float*)d_in[9];
    const float* Wih2b = (const float*)d_in[10];
    const float* Whh2b = (const float*)d_in[11];
    const float* bih2b = (const float*)d_in[12];
    const float* bhh2b = (const float*)d_in[13];
    float* out = (float*)d_out;
    float* ctx = out + (size_t)Wn * H1;

    float *p_gi2, *p_b2;
    cudaGetSymbolAddress((void**)&p_gi2, g_gi2);
    cudaGetSymbolAddress((void**)&p_b2,  g_b2);
    __nv_bfloat16 *pAp, *pW1, *pW2;
    cudaGetSymbolAddress((void**)&pAp, g_Ap);
    cudaGetSymbolAddress((void**)&pW1, g_Wp1);
    cudaGetSymbolAddress((void**)&pW2, g_Wp2);

    const int gsmem = 3 * STG;    // 110,592 B (plain)
    const int fsmem = 3 * FSTG;   // 96,768 B (fused)
    cudaFuncSetAttribute(gemm_mma,   cudaFuncAttributeMaxDynamicSharedMemorySize, gsmem);
    cudaFuncSetAttribute(gemm_fused, cudaFuncAttributeMaxDynamicSharedMemorySize, fsmem);
    dim3 ggf(H1 / 32, Wn / 128);        // (32, 16) fused mainloop
    dim3 gg2(2 * G2 / 128, Wn / 128);   // (48, 16) combined tail gemm

    convsplit_kernel<<<(G1 * Kd + 255) / 256, 256>>>(Whh1, pW1, nullptr, nullptr);  // 0 (+init)
    table_kernel<<<dim3(G1 / 64, Vn), 256>>>(emb, Wih1, bih1);                      // 1
    gru1_kernel<<<Wn, 256>>>(x, 0, bhh1);                                           // 2
    for (int t = 1; t < Cn; t++)
        gemm_fused<<<ggf, 256, fsmem>>>(pAp, pW1, x, out, bhh1, t);                 // 3..25

    convsplit_kernel<<<(G2 * Kd + 255) / 256, 256>>>(Wih2f, pW2, bih2f, p_b2);
    convsplit_kernel<<<(G2 * Kd + 255) / 256, 256>>>(Wih2b, pW2 + (size_t)G2 * KP, bih2b, p_b2 + G2);
    gemm_mma<<<gg2, 256, gsmem>>>(pAp, pW2, p_gi2, p_b2, 2 * G2);

    layer2_kernel<<<64, 512>>>(Whh2f, Whh2b, bhh2f, bhh2b, ctx);
}

// round 15
// speedup vs baseline: 1.9179x; 1.9179x over previous
#include <cuda_runtime.h>
#include <cuda_bf16.h>
#include <math.h>
#include <stdint.h>

#define Wn 2048
#define Cn 24
#define Vn 101
#define En 512
#define H1 1024
#define H2 1024
#define G1 3072
#define G2 3072
#define Kd 1024
#define KP 3072
#define STEPS 2048

// ---- scratch (__device__ globals; no allocations allowed) ----
__device__ float g_table[Vn * G1];
__device__ float g_h1[Wn * H1];
__device__ float g_gi2[Wn * 2 * G2];    // [word][fwd 3072 | bwd 3072]
__device__ float g_b2[2 * G2];          // [bih2f | bih2b]
__device__ float g_h2[2][2][H2];        // [dir][parity][dim]
__device__ unsigned g_bar2[2];
__device__ __nv_bfloat16 g_Ap[2][Wn * KP];       // DOUBLE-BUFFERED [Ah | Ah | Al]
__device__ __nv_bfloat16 g_Wp1[G1 * KP];         // [Wh | Wl | Wh]
__device__ __nv_bfloat16 g_Wp2[2 * G2 * KP];     // [W2f' ; W2b']

// =================== PTX helpers ===================
__device__ __forceinline__ uint32_t smem_u32(const void* p) {
    uint32_t a;
    asm("{ .reg .u64 t; cvta.to.shared.u64 t, %1; cvt.u32.u64 %0, t; }" : "=r"(a) : "l"(p));
    return a;
}
__device__ __forceinline__ void cpasync16(uint32_t dst, const void* src) {
    asm volatile("cp.async.cg.shared.global [%0], [%1], 16;" :: "r"(dst), "l"(src));
}
#define CP_COMMIT() asm volatile("cp.async.commit_group;" ::: "memory")
#define CP_WAIT1()  asm volatile("cp.async.wait_group 1;" ::: "memory")

__device__ __forceinline__ void ldm4(uint32_t* r, uint32_t addr) {
    asm volatile("ldmatrix.sync.aligned.m8n8.x4.shared.b16 {%0,%1,%2,%3}, [%4];"
        : "=r"(r[0]), "=r"(r[1]), "=r"(r[2]), "=r"(r[3]) : "r"(addr));
}
__device__ __forceinline__ void ldm2(uint32_t* r, uint32_t addr) {
    asm volatile("ldmatrix.sync.aligned.m8n8.x2.shared.b16 {%0,%1}, [%2];"
        : "=r"(r[0]), "=r"(r[1]) : "r"(addr));
}
__device__ __forceinline__ void mma16816(float* d, const uint32_t* a, const uint32_t* b) {
    asm volatile("mma.sync.aligned.m16n8k16.row.col.f32.bf16.bf16.f32 "
        "{%0,%1,%2,%3}, {%4,%5,%6,%7}, {%8,%9}, {%0,%1,%2,%3};"
        : "+f"(d[0]), "+f"(d[1]), "+f"(d[2]), "+f"(d[3])
        : "r"(a[0]), "r"(a[1]), "r"(a[2]), "r"(a[3]), "r"(b[0]), "r"(b[1]));
}
__device__ __forceinline__ void bar_arrive_release(unsigned* p) {
    asm volatile("red.release.gpu.global.add.u32 [%0], 1;" :: "l"(p) : "memory");
}
__device__ __forceinline__ unsigned ld_acquire(const unsigned* p) {
    unsigned v;
    asm volatile("ld.acquire.gpu.global.u32 %0, [%1];" : "=r"(v) : "l"(p) : "memory");
    return v;
}
__device__ __forceinline__ float tanh_fast(float x) {
    float y;
    asm("tanh.approx.f32 %0, %1;" : "=f"(y) : "f"(x));
    return y;
}
__device__ __forceinline__ float sigmoid_fast(float x) {
    return fmaf(tanh_fast(0.5f * x), 0.5f, 0.5f);
}

// =================== plain bf16 HMMA GEMM (R13-proven; tail only) ===================
#define STG 36864
#define HSTG 18432
#define NKIT (KP / 64)       // 48

__global__ void __launch_bounds__(256, 2) gemm_mma(
    const __nv_bfloat16* __restrict__ Ap, const __nv_bfloat16* __restrict__ Bp,
    float* __restrict__ C, const float* __restrict__ bias, int N) {
    extern __shared__ __align__(16) char smem[];
    const uint32_t sb = smem_u32(smem);
    const int tid = threadIdx.x, lane = tid & 31, warp = tid >> 5;
    const int wm = warp & 1, wn = warp >> 1;
    const int bm = blockIdx.y * 128, bn = blockIdx.x * 128;

    const int r1 = tid >> 2, c1 = tid & 3;
    const uint32_t oA = (uint32_t)r1 * 144 + (uint32_t)c1 * 16;
    const __nv_bfloat16* pa1 = Ap + (size_t)(bm + r1) * KP + c1 * 8;
    const __nv_bfloat16* pa2 = pa1 + (size_t)64 * KP;
    const __nv_bfloat16* pb1 = Bp + (size_t)(bn + r1) * KP + c1 * 8;
    const __nv_bfloat16* pb2 = pb1 + (size_t)64 * KP;

    const uint32_t aPre = (uint32_t)(wm * 64 + ((lane >> 3) & 1) * 8 + (lane & 7)) * 144
                        + (uint32_t)(lane >> 4) * 16;
    const uint32_t bPre = (uint32_t)(wn * 32 + (lane >> 4) * 8 + (lane & 7)) * 144
                        + (uint32_t)((lane >> 3) & 1) * 16;

    float acc[4][4][4];
#pragma unroll
    for (int i = 0; i < 4; i++)
#pragma unroll
        for (int j = 0; j < 4; j++)
#pragma unroll
            for (int q = 0; q < 4; q++) acc[i][j][q] = 0.f;

#define ISSUE(s, k0) do { \
    uint32_t as_ = sb + (s) * STG, bs_ = as_ + HSTG; \
    cpasync16(as_ + oA,              pa1 + (k0)); \
    cpasync16(as_ + oA + 64,         pa1 + (k0) + 32); \
    cpasync16(as_ + oA + 9216,       pa2 + (k0)); \
    cpasync16(as_ + oA + 9216 + 64,  pa2 + (k0) + 32); \
    cpasync16(bs_ + oA,              pb1 + (k0)); \
    cpasync16(bs_ + oA + 64,         pb1 + (k0) + 32); \
    cpasync16(bs_ + oA + 9216,       pb2 + (k0)); \
    cpasync16(bs_ + oA + 9216 + 64,  pb2 + (k0) + 32); \
} while (0)

    ISSUE(0, 0); CP_COMMIT();
    ISSUE(1, 64); CP_COMMIT();

    for (int it = 0; it < NKIT; it++) {
        CP_WAIT1();
        __syncthreads();
        if (it + 2 < NKIT) ISSUE((it + 2) % 3, (it + 2) * 64);
        CP_COMMIT();

        const uint32_t abase = sb + (it % 3) * STG;
        const uint32_t bbase = abase + HSTG;
#pragma unroll
        for (int ks = 0; ks < 4; ks++) {
            uint32_t a[4][4], bb[2][4];
#pragma unroll
            for (int ma = 0; ma < 4; ma++) ldm4(a[ma], abase + aPre + ma * 2304 + ks * 32);
#pragma unroll
            for (int nb = 0; nb < 2; nb++) ldm4(bb[nb], bbase + bPre + nb * 2304 + ks * 32);
#pragma unroll
            for (int ma = 0; ma < 4; ma++)
#pragma unroll
                for (int na = 0; na < 4; na++)
                    mma16816(acc[ma][na], a[ma], &bb[na >> 1][(na & 1) * 2]);
        }
    }
#undef ISSUE

    const int g = lane >> 2, t = lane & 3;
#pragma unroll
    for (int ma = 0; ma < 4; ma++) {
        int m0 = bm + wm * 64 + ma * 16 + g;
#pragma unroll
        for (int na = 0; na < 4; na++) {
            int col = bn + wn * 32 + na * 8 + t * 2;
            float b0 = bias[col], b1 = bias[col + 1];
            *(float2*)(C + (size_t)m0 * N + col) =
                make_float2(acc[ma][na][0] + b0, acc[ma][na][1] + b1);
            *(float2*)(C + (size_t)(m0 + 8) * N + col) =
                make_float2(acc[ma][na][2] + b0, acc[ma][na][3] + b1);
        }
    }
}

// =================== fused GEMM + GRU (race-fixed: reads Ain, writes Aout) ===================
#define FSTG 32256
#define FAB 18432

__global__ void __launch_bounds__(256, 2) gemm_fused(
    const __nv_bfloat16* __restrict__ Ain, __nv_bfloat16* __restrict__ Aout,
    const __nv_bfloat16* __restrict__ Bp,
    const int* __restrict__ x, float* __restrict__ out,
    const float* __restrict__ bhh, int tstep) {
    extern __shared__ __align__(16) char smem[];
    const uint32_t sb = smem_u32(smem);
    const int tid = threadIdx.x, lane = tid & 31, warp = tid >> 5;
    const int wm = warp & 1, wn = warp >> 1;
    const int bm = blockIdx.y * 128, j0 = blockIdx.x * 32;

    uint32_t soff[7];
    const __nv_bfloat16* src[7];
#pragma unroll
    for (int i = 0; i < 7; i++) {
        int id = tid + i * 256;
        int row = id >> 3, ch = id & 7;
        soff[i] = (uint32_t)row * 144 + (uint32_t)ch * 16;
        if (row < 128) {
            src[i] = Ain + (size_t)(bm + row) * KP + ch * 8;
        } else {
            int r2 = row - 128, gg = r2 >> 5, dl = r2 & 31;
            src[i] = Bp + (size_t)(gg * H1 + j0 + dl) * KP + ch * 8;
        }
    }

    const uint32_t aPre = (uint32_t)(wm * 64 + ((lane >> 3) & 1) * 8 + (lane & 7)) * 144
                        + (uint32_t)(lane >> 4) * 16;
    const uint32_t bPre = (uint32_t)FAB
                        + (uint32_t)(wn * 8 + (lane & 7)) * 144
                        + (uint32_t)((lane >> 3) & 1) * 16;

    float acc[4][3][4];
#pragma unroll
    for (int i = 0; i < 4; i++)
#pragma unroll
        for (int j = 0; j < 3; j++)
#pragma unroll
            for (int q = 0; q < 4; q++) acc[i][j][q] = 0.f;

#define FISSUE(s, k0) do { \
    uint32_t base_ = sb + (s) * FSTG; \
    cpasync16(base_ + soff[0], src[0] + (k0)); \
    cpasync16(base_ + soff[1], src[1] + (k0)); \
    cpasync16(base_ + soff[2], src[2] + (k0)); \
    cpasync16(base_ + soff[3], src[3] + (k0)); \
    cpasync16(base_ + soff[4], src[4] + (k0)); \
    cpasync16(base_ + soff[5], src[5] + (k0)); \
    cpasync16(base_ + soff[6], src[6] + (k0)); \
} while (0)

    FISSUE(0, 0); CP_COMMIT();
    FISSUE(1, 64); CP_COMMIT();

    for (int it = 0; it < NKIT; it++) {
        CP_WAIT1();
        __syncthreads();
        if (it + 2 < NKIT) FISSUE((it + 2) % 3, (it + 2) * 64);
        CP_COMMIT();

        const uint32_t abase = sb + (it % 3) * FSTG;
#pragma unroll
        for (int ks = 0; ks < 4; ks++) {
            uint32_t a[4][4], bb[3][2];
#pragma unroll
            for (int ma = 0; ma < 4; ma++) ldm4(a[ma], abase + aPre + ma * 2304 + ks * 32);
#pragma unroll
            for (int gg = 0; gg < 3; gg++) ldm2(bb[gg], abase + bPre + gg * 4608 + ks * 32);
#pragma unroll
            for (int ma = 0; ma < 4; ma++)
#pragma unroll
                for (int gg = 0; gg < 3; gg++)
                    mma16816(acc[ma][gg], a[ma], bb[gg]);
        }
    }
#undef FISSUE

    // ---- fused GRU epilogue (writes Aout: no overlap with Ain readers) ----
    const int g4 = lane >> 2, t4 = lane & 3;
    const int d = j0 + wn * 8 + t4 * 2;
    const float2 br = *(const float2*)(bhh + d);
    const float2 bz = *(const float2*)(bhh + H1 + d);
    const float2 bn2 = *(const float2*)(bhh + 2 * H1 + d);
    const bool last = (tstep == Cn - 1);

#pragma unroll
    for (int ma = 0; ma < 4; ma++) {
#pragma unroll
        for (int hf = 0; hf < 2; hf++) {
            const int w = bm + wm * 64 + ma * 16 + g4 + hf * 8;
            const int ch = x[w * Cn + tstep];
            const float* tb = g_table + ch * G1;
            const float2 ir = *(const float2*)(tb + d);
            const float2 iz = *(const float2*)(tb + H1 + d);
            const float2 in2 = *(const float2*)(tb + 2 * H1 + d);
            const float2 hp = *(const float2*)(g_h1 + (size_t)w * H1 + d);
            const int k0 = hf * 2;
            float r0 = sigmoid_fast(ir.x + acc[ma][0][k0 + 0] + br.x);
            float r1 = sigmoid_fast(ir.y + acc[ma][0][k0 + 1] + br.y);
            float z0 = sigmoid_fast(iz.x + acc[ma][1][k0 + 0] + bz.x);
            float z1 = sigmoid_fast(iz.y + acc[ma][1][k0 + 1] + bz.y);
            float n0 = tanh_fast(in2.x + r0 * (acc[ma][2][k0 + 0] + bn2.x));
            float n1 = tanh_fast(in2.y + r1 * (acc[ma][2][k0 + 1] + bn2.y));
            float h0 = (1.f - z0) * n0 + z0 * hp.x;
            float h1 = (1.f - z1) * n1 + z1 * hp.y;
            *(float2*)(g_h1 + (size_t)w * H1 + d) = make_float2(h0, h1);
            union { __nv_bfloat162 b; uint32_t u; } PH, PL;
            PH.b = __floats2bfloat162_rn(h0, h1);
            float l0 = h0 - __bfloat162float(__float2bfloat16(h0));
            float l1 = h1 - __bfloat162float(__float2bfloat16(h1));
            PL.b = __floats2bfloat162_rn(l0, l1);
            __nv_bfloat16* arow = Aout + (size_t)w * KP;
            *(uint32_t*)(arow + d) = PH.u;
            *(uint32_t*)(arow + Kd + d) = PH.u;
            *(uint32_t*)(arow + 2 * Kd + d) = PL.u;
            if (last) *(float2*)(out + (size_t)w * H1 + d) = make_float2(h0, h1);
        }
    }
}

// =================== conversions (+ per-replay init, + bias copy) ===================
__global__ void convsplit_kernel(const float* __restrict__ w,
                                 __nv_bfloat16* __restrict__ wp,
                                 const float* __restrict__ bsrc,
                                 float* __restrict__ bdst) {
    int i = blockIdx.x * 256 + threadIdx.x;
    if (i < 4 * H2) ((float*)g_h2)[i] = 0.f;
    if (i < 2) g_bar2[i] = 0u;
    if (bdst && i < G2 * 3) bdst[i] = bsrc[i];
    if (i >= G1 * Kd) return;
    int r = i >> 10, k = i & 1023;
    float v = w[i];
    __nv_bfloat16 h = __float2bfloat16(v);
    __nv_bfloat16 l = __float2bfloat16(v - __bfloat162float(h));
    __nv_bfloat16* row = wp + (size_t)r * KP;
    row[k] = h; row[Kd + k] = l; row[2 * Kd + k] = h;
}

__global__ void table_kernel(const float* __restrict__ emb,
                             const float* __restrict__ Wih1,
                             const float* __restrict__ bih1) {
    __shared__ __align__(16) float e[En];
    int v = blockIdx.y;
    int tid = threadIdx.x, warp = tid >> 5, lane = tid & 31;
    for (int i = tid; i < En; i += 256) e[i] = emb[v * En + i];
    __syncthreads();
    int rbase = blockIdx.x * 64 + warp * 8;
    for (int rr = 0; rr < 8; rr++) {
        int row = rbase + rr;
        const float4* wp = (const float4*)(Wih1 + (size_t)row * En);
        const float4* ep = (const float4*)e;
        float s = 0.f;
#pragma unroll
        for (int k = 0; k < 4; k++) {
            float4 wv = wp[lane + 32 * k];
            float4 ev = ep[lane + 32 * k];
            s += wv.x * ev.x + wv.y * ev.y + wv.z * ev.z + wv.w * ev.w;
        }
        for (int off = 16; off; off >>= 1) s += __shfl_xor_sync(0xffffffffu, s, off);
        if (lane == 0) g_table[v * G1 + row] = s + bih1[row];
    }
}

// ---- layer-1 t=0 pointwise (h0 = 0 -> gh = bhh); writes A buf0 ----
__global__ void gru1_kernel(const int* __restrict__ x,
                            const float* __restrict__ bhh,
                            __nv_bfloat16* __restrict__ Aout) {
    const int w = blockIdx.x, tid = threadIdx.x, j = tid * 4;
    const int ch = x[w * Cn + 0];
    const float* tb = g_table + ch * G1;
    float4 ir = *(const float4*)(tb + j);
    float4 iz = *(const float4*)(tb + H1 + j);
    float4 in4 = *(const float4*)(tb + 2 * H1 + j);
    float4 hr = *(const float4*)(bhh + j);
    float4 hz = *(const float4*)(bhh + H1 + j);
    float4 hg = *(const float4*)(bhh + 2 * H1 + j);
    float hn[4], hl[4];
    {
        const float irv[4] = {ir.x, ir.y, ir.z, ir.w};
        const float izv[4] = {iz.x, iz.y, iz.z, iz.w};
        const float inv[4] = {in4.x, in4.y, in4.z, in4.w};
        const float hrv[4] = {hr.x, hr.y, hr.z, hr.w};
        const float hzv[4] = {hz.x, hz.y, hz.z, hz.w};
        const float hgv[4] = {hg.x, hg.y, hg.z, hg.w};
#pragma unroll
        for (int q = 0; q < 4; q++) {
            float r = sigmoid_fast(irv[q] + hrv[q]);
            float z = sigmoid_fast(izv[q] + hzv[q]);
            float n = tanh_fast(inv[q] + r * hgv[q]);
            hn[q] = (1.f - z) * n;
        }
    }
    *(float4*)(g_h1 + (size_t)w * H1 + j) = make_float4(hn[0], hn[1], hn[2], hn[3]);
    union { __nv_bfloat162 h2[2]; uint2 u; } PH, PL;
    PH.h2[0] = __floats2bfloat162_rn(hn[0], hn[1]);
    PH.h2[1] = __floats2bfloat162_rn(hn[2], hn[3]);
#pragma unroll
    for (int q = 0; q < 4; q++) {
        __nv_bfloat16 hb = __float2bfloat16(hn[q]);
        hl[q] = hn[q] - __bfloat162float(hb);
    }
    PL.h2[0] = __floats2bfloat162_rn(hl[0], hl[1]);
    PL.h2[1] = __floats2bfloat162_rn(hl[2], hl[3]);
    __nv_bfloat16* arow = Aout + (size_t)w * KP;
    *(uint2*)(arow + j) = PH.u;
    *(uint2*)(arow + Kd + j) = PH.u;
    *(uint2*)(arow + 2 * Kd + j) = PL.u;
}

// ---- layer-2 persistent bi-GRU: R13-proven (128 CTAs x 256, fan-in 64, hot poll) ----
__global__ void __launch_bounds__(256, 1) layer2_kernel(
    const float* __restrict__ Whhf, const float* __restrict__ Whhb,
    const float* __restrict__ bhhf, const float* __restrict__ bhhb,
    float* __restrict__ ctx) {
    __shared__ __align__(16) float hs[1024];
    const int tid = threadIdx.x, warp = tid >> 5, lane = tid & 31;
    const int cta = blockIdx.x, dir = cta >> 6, j0 = (cta & 63) << 4;
    const float* Whh = dir ? Whhb : Whhf;
    const float* bhh = dir ? bhhb : bhhf;
    const float* GI  = g_gi2 + dir * G2;
    unsigned* barp = &g_bar2[dir];
    const int d0 = j0 + 2 * warp;

    float4 wreg[6][8];
#pragma unroll
    for (int u = 0; u < 2; u++)
#pragma unroll
        for (int gg = 0; gg < 3; gg++) {
            const float4* wp = (const float4*)(Whh + (size_t)(gg * H2 + d0 + u) * H2);
#pragma unroll
            for (int c = 0; c < 8; c++) wreg[u * 3 + gg][c] = wp[c * 32 + lane];
        }
    float bg[6];
#pragma unroll
    for (int u = 0; u < 2; u++)
#pragma unroll
        for (int gg = 0; gg < 3; gg++) bg[u * 3 + gg] = bhh[gg * H2 + d0 + u];

    for (int t = 0; t < STEPS; t++) {
        const int wd = dir ? (STEPS - 1 - t) : t;
        const float* gi = GI + (size_t)wd * (2 * G2);

        ((float4*)hs)[tid] = __ldcg(((const float4*)g_h2[dir][t & 1]) + tid);
        float giv[6];
        if (lane == 0) {
#pragma unroll
            for (int u = 0; u < 2; u++)
#pragma unroll
                for (int gg = 0; gg < 3; gg++) giv[u * 3 + gg] = gi[gg * H2 + d0 + u];
        }
        __syncthreads();

        float acc[6] = {0.f, 0.f, 0.f, 0.f, 0.f, 0.f};
#pragma unroll
        for (int c = 0; c < 8; c++) {
            float4 h4 = ((const float4*)hs)[c * 32 + lane];
#pragma unroll
            for (int rr = 0; rr < 6; rr++)
                acc[rr] += wreg[rr][c].x * h4.x + wreg[rr][c].y * h4.y
                         + wreg[rr][c].z * h4.z + wreg[rr][c].w * h4.w;
        }
#pragma unroll
        for (int off = 16; off; off >>= 1)
#pragma unroll
            for (int rr = 0; rr < 6; rr++)
                acc[rr] += __shfl_xor_sync(0xffffffffu, acc[rr], off);

        if (lane == 0) {
            float hnew[2];
#pragma unroll
            for (int u = 0; u < 2; u++) {
                float r = sigmoid_fast(giv[u * 3 + 0] + acc[u * 3 + 0] + bg[u * 3 + 0]);
                float z = sigmoid_fast(giv[u * 3 + 1] + acc[u * 3 + 1] + bg[u * 3 + 1]);
                float n = tanh_fast(giv[u * 3 + 2] + r * (acc[u * 3 + 2] + bg[u * 3 + 2]));
                hnew[u] = (1.f - z) * n + z * hs[d0 + u];
            }
            *(float2*)(ctx + (size_t)wd * (2 * H2) + dir * H2 + d0) = make_float2(hnew[0], hnew[1]);
            __stcg((float2*)&g_h2[dir][(t + 1) & 1][d0], make_float2(hnew[0], hnew[1]));
        }
        __syncthreads();

        if (tid == 0) {
            bar_arrive_release(barp);
            unsigned target = 64u * (unsigned)(t + 1);
            while (ld_acquire(barp) < target) { }
        }
        __syncthreads();
    }
}

extern "C" void kernel_launch(void* const* d_in, const int* in_sizes, int n_in,
                              void* d_out, int out_size) {
    const int*   x     = (const int*)d_in[0];
    const float* emb   = (const float*)d_in[1];
    const float* Wih1  = (const float*)d_in[2];
    const float* Whh1  = (const float*)d_in[3];
    const float* bih1  = (const float*)d_in[4];
    const float* bhh1  = (const float*)d_in[5];
    const float* Wih2f = (const float*)d_in[6];
    const float* Whh2f = (const float*)d_in[7];
    const float* bih2f = (const float*)d_in[8];
    const float* bhh2f = (const float*)d_in[9];
    const float* Wih2b = (const float*)d_in[10];
    const float* Whh2b = (const float*)d_in[11];
    const float* bih2b = (const float*)d_in[12];
    const float* bhh2b = (const float*)d_in[13];
    float* out = (float*)d_out;
    float* ctx = out + (size_t)Wn * H1;

    float *p_gi2, *p_b2;
    cudaGetSymbolAddress((void**)&p_gi2, g_gi2);
    cudaGetSymbolAddress((void**)&p_b2,  g_b2);
    __nv_bfloat16 *pAp, *pW1, *pW2;
    cudaGetSymbolAddress((void**)&pAp, g_Ap);
    cudaGetSymbolAddress((void**)&pW1, g_Wp1);
    cudaGetSymbolAddress((void**)&pW2, g_Wp2);
    __nv_bfloat16* buf[2] = { pAp, pAp + (size_t)Wn * KP };

    const int gsmem = 3 * STG;
    const int fsmem = 3 * FSTG;
    cudaFuncSetAttribute(gemm_mma,   cudaFuncAttributeMaxDynamicSharedMemorySize, gsmem);
    cudaFuncSetAttribute(gemm_fused, cudaFuncAttributeMaxDynamicSharedMemorySize, fsmem);
    dim3 ggf(H1 / 32, Wn / 128);        // (32, 16) fused mainloop
    dim3 gg2(2 * G2 / 128, Wn / 128);   // (48, 16) combined tail gemm

    convsplit_kernel<<<(G1 * Kd + 255) / 256, 256>>>(Whh1, pW1, nullptr, nullptr);  // 0 (+init)
    table_kernel<<<dim3(G1 / 64, Vn), 256>>>(emb, Wih1, bih1);                      // 1
    gru1_kernel<<<Wn, 256>>>(x, bhh1, buf[0]);                                      // 2  A(0)->buf0
    for (int t = 1; t < Cn; t++)                                                    // A(t)->buf[t&1]
        gemm_fused<<<ggf, 256, fsmem>>>(buf[(t + 1) & 1], buf[t & 1], pW1, x, out, bhh1, t);

    convsplit_kernel<<<(G2 * Kd + 255) / 256, 256>>>(Wih2f, pW2, bih2f, p_b2);
    convsplit_kernel<<<(G2 * Kd + 255) / 256, 256>>>(Wih2b, pW2 + (size_t)G2 * KP, bih2b, p_b2 + G2);
    gemm_mma<<<gg2, 256, gsmem>>>(buf[(Cn - 1) & 1], pW2, p_gi2, p_b2, 2 * G2);

    layer2_kernel<<<128, 256>>>(Whh2f, Whh2b, bhh2f, bhh2b, ctx);
}

// round 16
// speedup vs baseline: 1.9915x; 1.0384x over previous
#include <cuda_runtime.h>
#include <cuda_bf16.h>
#include <math.h>
#include <stdint.h>

#define Wn 2048
#define Cn 24
#define Vn 101
#define En 512
#define H1 1024
#define H2 1024
#define G1 3072
#define G2 3072
#define Kd 1024
#define KA 2048              // A buffer: [Ah | Al]
#define STEPS 2048

// ---- scratch (__device__ globals; no allocations allowed) ----
__device__ float g_table[Vn * G1];
__device__ float g_h1[Wn * H1];
__device__ float g_gi2[Wn * 2 * G2];    // [word][fwd 3072 | bwd 3072]
__device__ float g_b2[2 * G2];          // [bih2f | bih2b]
__device__ float g_h2[2][2][H2];        // [dir][parity][dim]
__device__ unsigned g_bar2[2];
__device__ __nv_bfloat16 g_Ap[2][Wn * KA];       // double-buffered [Ah | Al]
__device__ __nv_bfloat16 g_W1h[G1 * Kd], g_W1l[G1 * Kd];
__device__ __nv_bfloat16 g_W2h[2 * G2 * Kd], g_W2l[2 * G2 * Kd];   // [f ; b]

// =================== PTX helpers ===================
__device__ __forceinline__ uint32_t smem_u32(const void* p) {
    uint32_t a;
    asm("{ .reg .u64 t; cvta.to.shared.u64 t, %1; cvt.u32.u64 %0, t; }" : "=r"(a) : "l"(p));
    return a;
}
__device__ __forceinline__ void cpasync16(uint32_t dst, const void* src) {
    asm volatile("cp.async.cg.shared.global [%0], [%1], 16;" :: "r"(dst), "l"(src));
}
#define CP_COMMIT() asm volatile("cp.async.commit_group;" ::: "memory")
#define CP_WAIT1()  asm volatile("cp.async.wait_group 1;" ::: "memory")

__device__ __forceinline__ void ldm4(uint32_t* r, uint32_t addr) {
    asm volatile("ldmatrix.sync.aligned.m8n8.x4.shared.b16 {%0,%1,%2,%3}, [%4];"
        : "=r"(r[0]), "=r"(r[1]), "=r"(r[2]), "=r"(r[3]) : "r"(addr));
}
__device__ __forceinline__ void ldm2(uint32_t* r, uint32_t addr) {
    asm volatile("ldmatrix.sync.aligned.m8n8.x2.shared.b16 {%0,%1}, [%2];"
        : "=r"(r[0]), "=r"(r[1]) : "r"(addr));
}
__device__ __forceinline__ void mma16816(float* d, const uint32_t* a, const uint32_t* b) {
    asm volatile("mma.sync.aligned.m16n8k16.row.col.f32.bf16.bf16.f32 "
        "{%0,%1,%2,%3}, {%4,%5,%6,%7}, {%8,%9}, {%0,%1,%2,%3};"
        : "+f"(d[0]), "+f"(d[1]), "+f"(d[2]), "+f"(d[3])
        : "r"(a[0]), "r"(a[1]), "r"(a[2]), "r"(a[3]), "r"(b[0]), "r"(b[1]));
}
__device__ __forceinline__ void bar_arrive_release(unsigned* p) {
    asm volatile("red.release.gpu.global.add.u32 [%0], 1;" :: "l"(p) : "memory");
}
__device__ __forceinline__ unsigned ld_acquire(const unsigned* p) {
    unsigned v;
    asm volatile("ld.acquire.gpu.global.u32 %0, [%1];" : "=r"(v) : "l"(p) : "memory");
    return v;
}
__device__ __forceinline__ float tanh_fast(float x) {
    float y;
    asm("tanh.approx.f32 %0, %1;" : "=f"(y) : "f"(x));
    return y;
}
__device__ __forceinline__ float sigmoid_fast(float x) {
    return fmaf(tanh_fast(0.5f * x), 0.5f, 0.5f);
}

// =================== de-duplicated split GEMM core geometry ===================
// Stage: 448 rows x 80B: [Ah 0..127 | Al 128..255 | Wh 256..351 | Wl 352..447],
// each row = 32 k of bf16 (64B data + 16B pad). 3 stages = 107,520 B -> occ 2.
// Per super-iter (k32): 3 passes AhWh + AlWh + AhWl from one staging.
#define SSTG 35840
#define ALOFF 10240
#define WHOFF 20480
#define WLOFF 28160
#define NSUP (Kd / 32)       // 32

// Shared mainloop macro-body via includes would be cleaner; keep two kernels.

// ---- staging map: 1792 chunks of 16B; id = tid + i*256; row=id>>2, ch=id&3 ----
#define STAGE_PTRS(AIN, BH, BL, BROW_EXPR) \
    uint32_t soff[7]; const __nv_bfloat16* src[7]; \
    _Pragma("unroll") \
    for (int i = 0; i < 7; i++) { \
        int id = tid + i * 256; \
        int row = id >> 2, ch = id & 3; \
        soff[i] = (uint32_t)row * 80 + (uint32_t)ch * 16; \
        const __nv_bfloat16* s; \
        if (row < 128)      s = (AIN) + (size_t)(bm + row) * KA + ch * 8; \
        else if (row < 256) s = (AIN) + (size_t)(bm + row - 128) * KA + Kd + ch * 8; \
        else if (row < 352) { int r2 = row - 256; s = (BH) + (size_t)(BROW_EXPR) * Kd + ch * 8; } \
        else                { int r2 = row - 352; s = (BL) + (size_t)(BROW_EXPR) * Kd + ch * 8; } \
        src[i] = s; \
    }

#define GISSUE(s, k0) do { \
    uint32_t base_ = sb + (s) * SSTG; \
    cpasync16(base_ + soff[0], src[0] + (k0)); \
    cpasync16(base_ + soff[1], src[1] + (k0)); \
    cpasync16(base_ + soff[2], src[2] + (k0)); \
    cpasync16(base_ + soff[3], src[3] + (k0)); \
    cpasync16(base_ + soff[4], src[4] + (k0)); \
    cpasync16(base_ + soff[5], src[5] + (k0)); \
    cpasync16(base_ + soff[6], src[6] + (k0)); \
} while (0)

// mainloop: fills acc[4][3][4]
#define GEMM_MAINLOOP() \
    GISSUE(0, 0); CP_COMMIT(); \
    GISSUE(1, 32); CP_COMMIT(); \
    for (int c = 0; c < NSUP; c++) { \
        CP_WAIT1(); \
        __syncthreads(); \
        if (c + 2 < NSUP) GISSUE((c + 2) % 3, (c + 2) * 32); \
        CP_COMMIT(); \
        const uint32_t abase = sb + (c % 3) * SSTG; \
        _Pragma("unroll") \
        for (int ks = 0; ks < 2; ks++) { \
            uint32_t ah[4][4], al[4][4], bh[3][2], bl[3][2]; \
            _Pragma("unroll") \
            for (int ma = 0; ma < 4; ma++) ldm4(ah[ma], abase + aPre + ma * 1280 + ks * 32); \
            _Pragma("unroll") \
            for (int gg = 0; gg < 3; gg++) ldm2(bh[gg], abase + WHOFF + bPre + gg * 2560 + ks * 32); \
            _Pragma("unroll") \
            for (int ma = 0; ma < 4; ma++) \
                _Pragma("unroll") \
                for (int gg = 0; gg < 3; gg++) mma16816(acc[ma][gg], ah[ma], bh[gg]); \
            _Pragma("unroll") \
            for (int ma = 0; ma < 4; ma++) ldm4(al[ma], abase + ALOFF + aPre + ma * 1280 + ks * 32); \
            _Pragma("unroll") \
            for (int ma = 0; ma < 4; ma++) \
                _Pragma("unroll") \
                for (int gg = 0; gg < 3; gg++) mma16816(acc[ma][gg], al[ma], bh[gg]); \
            _Pragma("unroll") \
            for (int gg = 0; gg < 3; gg++) ldm2(bl[gg], abase + WLOFF + bPre + gg * 2560 + ks * 32); \
            _Pragma("unroll") \
            for (int ma = 0; ma < 4; ma++) \
                _Pragma("unroll") \
                for (int gg = 0; gg < 3; gg++) mma16816(acc[ma][gg], ah[ma], bl[gg]); \
        } \
    }

// =================== fused GEMM + GRU (layer-1 mainloop) ===================
__global__ void __launch_bounds__(256, 2) gemm_fused(
    const __nv_bfloat16* __restrict__ Ain, __nv_bfloat16* __restrict__ Aout,
    const __nv_bfloat16* __restrict__ Wh, const __nv_bfloat16* __restrict__ Wl,
    const int* __restrict__ x, float* __restrict__ out,
    const float* __restrict__ bhh, int tstep) {
    extern __shared__ __align__(16) char smem[];
    const uint32_t sb = smem_u32(smem);
    const int tid = threadIdx.x, lane = tid & 31, warp = tid >> 5;
    const int wm = warp & 1, wn = warp >> 1;
    const int bm = blockIdx.y * 128, j0 = blockIdx.x * 32;

    STAGE_PTRS(Ain, Wh, Wl, (r2 >> 5) * H1 + j0 + (r2 & 31))

    const uint32_t aPre = (uint32_t)(wm * 64 + ((lane >> 3) & 1) * 8 + (lane & 7)) * 80
                        + (uint32_t)(lane >> 4) * 16;
    const uint32_t bPre = (uint32_t)(wn * 8 + (lane & 7)) * 80
                        + (uint32_t)((lane >> 3) & 1) * 16;

    float acc[4][3][4];
#pragma unroll
    for (int i = 0; i < 4; i++)
#pragma unroll
        for (int j = 0; j < 3; j++)
#pragma unroll
            for (int q = 0; q < 4; q++) acc[i][j][q] = 0.f;

    GEMM_MAINLOOP()

    // ---- fused GRU epilogue ----
    const int g4 = lane >> 2, t4 = lane & 3;
    const int d = j0 + wn * 8 + t4 * 2;
    const float2 br = *(const float2*)(bhh + d);
    const float2 bz = *(const float2*)(bhh + H1 + d);
    const float2 bn2 = *(const float2*)(bhh + 2 * H1 + d);
    const bool last = (tstep == Cn - 1);

#pragma unroll
    for (int ma = 0; ma < 4; ma++) {
#pragma unroll
        for (int hf = 0; hf < 2; hf++) {
            const int w = bm + wm * 64 + ma * 16 + g4 + hf * 8;
            const int ch = x[w * Cn + tstep];
            const float* tb = g_table + ch * G1;
            const float2 ir = *(const float2*)(tb + d);
            const float2 iz = *(const float2*)(tb + H1 + d);
            const float2 in2 = *(const float2*)(tb + 2 * H1 + d);
            const float2 hp = *(const float2*)(g_h1 + (size_t)w * H1 + d);
            const int k0 = hf * 2;
            float r0 = sigmoid_fast(ir.x + acc[ma][0][k0 + 0] + br.x);
            float r1 = sigmoid_fast(ir.y + acc[ma][0][k0 + 1] + br.y);
            float z0 = sigmoid_fast(iz.x + acc[ma][1][k0 + 0] + bz.x);
            float z1 = sigmoid_fast(iz.y + acc[ma][1][k0 + 1] + bz.y);
            float n0 = tanh_fast(in2.x + r0 * (acc[ma][2][k0 + 0] + bn2.x));
            float n1 = tanh_fast(in2.y + r1 * (acc[ma][2][k0 + 1] + bn2.y));
            float h0 = (1.f - z0) * n0 + z0 * hp.x;
            float h1 = (1.f - z1) * n1 + z1 * hp.y;
            *(float2*)(g_h1 + (size_t)w * H1 + d) = make_float2(h0, h1);
            union { __nv_bfloat162 b; uint32_t u; } PH, PL;
            PH.b = __floats2bfloat162_rn(h0, h1);
            float l0 = h0 - __bfloat162float(__float2bfloat16(h0));
            float l1 = h1 - __bfloat162float(__float2bfloat16(h1));
            PL.b = __floats2bfloat162_rn(l0, l1);
            __nv_bfloat16* arow = Aout + (size_t)w * KA;
            *(uint32_t*)(arow + d) = PH.u;
            *(uint32_t*)(arow + Kd + d) = PL.u;
            if (last) *(float2*)(out + (size_t)w * H1 + d) = make_float2(h0, h1);
        }
    }
}

// =================== tail GEMM (plain C += bias; 96-col tiles) ===================
__global__ void __launch_bounds__(256, 2) gemm_tail(
    const __nv_bfloat16* __restrict__ Ain,
    const __nv_bfloat16* __restrict__ Wh, const __nv_bfloat16* __restrict__ Wl,
    float* __restrict__ C, const float* __restrict__ bias, int NN) {
    extern __shared__ __align__(16) char smem[];
    const uint32_t sb = smem_u32(smem);
    const int tid = threadIdx.x, lane = tid & 31, warp = tid >> 5;
    const int wm = warp & 1, wn = warp >> 1;
    const int bm = blockIdx.y * 128, colb = blockIdx.x * 96;

    STAGE_PTRS(Ain, Wh, Wl, colb + r2)

    const uint32_t aPre = (uint32_t)(wm * 64 + ((lane >> 3) & 1) * 8 + (lane & 7)) * 80
                        + (uint32_t)(lane >> 4) * 16;
    const uint32_t bPre = (uint32_t)(wn * 8 + (lane & 7)) * 80
                        + (uint32_t)((lane >> 3) & 1) * 16;

    float acc[4][3][4];
#pragma unroll
    for (int i = 0; i < 4; i++)
#pragma unroll
        for (int j = 0; j < 3; j++)
#pragma unroll
            for (int q = 0; q < 4; q++) acc[i][j][q] = 0.f;

    GEMM_MAINLOOP()

    const int g4 = lane >> 2, t4 = lane & 3;
#pragma unroll
    for (int ma = 0; ma < 4; ma++) {
        int m0 = bm + wm * 64 + ma * 16 + g4;
#pragma unroll
        for (int gg = 0; gg < 3; gg++) {
            int col = colb + gg * 32 + wn * 8 + t4 * 2;
            float b0 = bias[col], b1 = bias[col + 1];
            *(float2*)(C + (size_t)m0 * NN + col) =
                make_float2(acc[ma][gg][0] + b0, acc[ma][gg][1] + b1);
            *(float2*)(C + (size_t)(m0 + 8) * NN + col) =
                make_float2(acc[ma][gg][2] + b0, acc[ma][gg][3] + b1);
        }
    }
}

// =================== conversions (+ per-replay init, + bias copy) ===================
__global__ void convsplit_kernel(const float* __restrict__ w,
                                 __nv_bfloat16* __restrict__ wh,
                                 __nv_bfloat16* __restrict__ wl,
                                 const float* __restrict__ bsrc,
                                 float* __restrict__ bdst) {
    int i = blockIdx.x * 256 + threadIdx.x;
    if (i < 4 * H2) ((float*)g_h2)[i] = 0.f;
    if (i < 2) g_bar2[i] = 0u;
    if (bdst && i < G2 * 3) bdst[i] = bsrc[i];
    if (i >= G1 * Kd) return;
    float v = w[i];
    __nv_bfloat16 h = __float2bfloat16(v);
    wh[i] = h;
    wl[i] = __float2bfloat16(v - __bfloat162float(h));
}

__global__ void table_kernel(const float* __restrict__ emb,
                             const float* __restrict__ Wih1,
                             const float* __restrict__ bih1) {
    __shared__ __align__(16) float e[En];
    int v = blockIdx.y;
    int tid = threadIdx.x, warp = tid >> 5, lane = tid & 31;
    for (int i = tid; i < En; i += 256) e[i] = emb[v * En + i];
    __syncthreads();
    int rbase = blockIdx.x * 64 + warp * 8;
    for (int rr = 0; rr < 8; rr++) {
        int row = rbase + rr;
        const float4* wp = (const float4*)(Wih1 + (size_t)row * En);
        const float4* ep = (const float4*)e;
        float s = 0.f;
#pragma unroll
        for (int k = 0; k < 4; k++) {
            float4 wv = wp[lane + 32 * k];
            float4 ev = ep[lane + 32 * k];
            s += wv.x * ev.x + wv.y * ev.y + wv.z * ev.z + wv.w * ev.w;
        }
        for (int off = 16; off; off >>= 1) s += __shfl_xor_sync(0xffffffffu, s, off);
        if (lane == 0) g_table[v * G1 + row] = s + bih1[row];
    }
}

// ---- layer-1 t=0 pointwise (h0 = 0 -> gh = bhh); writes A buf0 ----
__global__ void gru1_kernel(const int* __restrict__ x,
                            const float* __restrict__ bhh,
                            __nv_bfloat16* __restrict__ Aout) {
    const int w = blockIdx.x, tid = threadIdx.x, j = tid * 4;
    const int ch = x[w * Cn + 0];
    const float* tb = g_table + ch * G1;
    float4 ir = *(const float4*)(tb + j);
    float4 iz = *(const float4*)(tb + H1 + j);
    float4 in4 = *(const float4*)(tb + 2 * H1 + j);
    float4 hr = *(const float4*)(bhh + j);
    float4 hz = *(const float4*)(bhh + H1 + j);
    float4 hg = *(const float4*)(bhh + 2 * H1 + j);
    float hn[4], hl[4];
    {
        const float irv[4] = {ir.x, ir.y, ir.z, ir.w};
        const float izv[4] = {iz.x, iz.y, iz.z, iz.w};
        const float inv[4] = {in4.x, in4.y, in4.z, in4.w};
        const float hrv[4] = {hr.x, hr.y, hr.z, hr.w};
        const float hzv[4] = {hz.x, hz.y, hz.z, hz.w};
        const float hgv[4] = {hg.x, hg.y, hg.z, hg.w};
#pragma unroll
        for (int q = 0; q < 4; q++) {
            float r = sigmoid_fast(irv[q] + hrv[q]);
            float z = sigmoid_fast(izv[q] + hzv[q]);
            float n = tanh_fast(inv[q] + r * hgv[q]);
            hn[q] = (1.f - z) * n;
        }
    }
    *(float4*)(g_h1 + (size_t)w * H1 + j) = make_float4(hn[0], hn[1], hn[2], hn[3]);
    union { __nv_bfloat162 h2[2]; uint2 u; } PH, PL;
    PH.h2[0] = __floats2bfloat162_rn(hn[0], hn[1]);
    PH.h2[1] = __floats2bfloat162_rn(hn[2], hn[3]);
#pragma unroll
    for (int q = 0; q < 4; q++) {
        __nv_bfloat16 hb = __float2bfloat16(hn[q]);
        hl[q] = hn[q] - __bfloat162float(hb);
    }
    PL.h2[0] = __floats2bfloat162_rn(hl[0], hl[1]);
    PL.h2[1] = __floats2bfloat162_rn(hl[2], hl[3]);
    __nv_bfloat16* arow = Aout + (size_t)w * KA;
    *(uint2*)(arow + j) = PH.u;
    *(uint2*)(arow + Kd + j) = PL.u;
}

// ---- layer-2 persistent bi-GRU: R13-proven verbatim ----
__global__ void __launch_bounds__(256, 1) layer2_kernel(
    const float* __restrict__ Whhf, const float* __restrict__ Whhb,
    const float* __restrict__ bhhf, const float* __restrict__ bhhb,
    float* __restrict__ ctx) {
    __shared__ __align__(16) float hs[1024];
    const int tid = threadIdx.x, warp = tid >> 5, lane = tid & 31;
    const int cta = blockIdx.x, dir = cta >> 6, j0 = (cta & 63) << 4;
    const float* Whh = dir ? Whhb : Whhf;
    const float* bhh = dir ? bhhb : bhhf;
    const float* GI  = g_gi2 + dir * G2;
    unsigned* barp = &g_bar2[dir];
    const int d0 = j0 + 2 * warp;

    float4 wreg[6][8];
#pragma unroll
    for (int u = 0; u < 2; u++)
#pragma unroll
        for (int gg = 0; gg < 3; gg++) {
            const float4* wp = (const float4*)(Whh + (size_t)(gg * H2 + d0 + u) * H2);
#pragma unroll
            for (int c = 0; c < 8; c++) wreg[u * 3 + gg][c] = wp[c * 32 + lane];
        }
    float bg[6];
#pragma unroll
    for (int u = 0; u < 2; u++)
#pragma unroll
        for (int gg = 0; gg < 3; gg++) bg[u * 3 + gg] = bhh[gg * H2 + d0 + u];

    for (int t = 0; t < STEPS; t++) {
        const int wd = dir ? (STEPS - 1 - t) : t;
        const float* gi = GI + (size_t)wd * (2 * G2);

        ((float4*)hs)[tid] = __ldcg(((const float4*)g_h2[dir][t & 1]) + tid);
        float giv[6];
        if (lane == 0) {
#pragma unroll
            for (int u = 0; u < 2; u++)
#pragma unroll
                for (int gg = 0; gg < 3; gg++) giv[u * 3 + gg] = gi[gg * H2 + d0 + u];
        }
        __syncthreads();

        float acc[6] = {0.f, 0.f, 0.f, 0.f, 0.f, 0.f};
#pragma unroll
        for (int c = 0; c < 8; c++) {
            float4 h4 = ((const float4*)hs)[c * 32 + lane];
#pragma unroll
            for (int rr = 0; rr < 6; rr++)
                acc[rr] += wreg[rr][c].x * h4.x + wreg[rr][c].y * h4.y
                         + wreg[rr][c].z * h4.z + wreg[rr][c].w * h4.w;
        }
#pragma unroll
        for (int off = 16; off; off >>= 1)
#pragma unroll
            for (int rr = 0; rr < 6; rr++)
                acc[rr] += __shfl_xor_sync(0xffffffffu, acc[rr], off);

        if (lane == 0) {
            float hnew[2];
#pragma unroll
            for (int u = 0; u < 2; u++) {
                float r = sigmoid_fast(giv[u * 3 + 0] + acc[u * 3 + 0] + bg[u * 3 + 0]);
                float z = sigmoid_fast(giv[u * 3 + 1] + acc[u * 3 + 1] + bg[u * 3 + 1]);
                float n = tanh_fast(giv[u * 3 + 2] + r * (acc[u * 3 + 2] + bg[u * 3 + 2]));
                hnew[u] = (1.f - z) * n + z * hs[d0 + u];
            }
            *(float2*)(ctx + (size_t)wd * (2 * H2) + dir * H2 + d0) = make_float2(hnew[0], hnew[1]);
            __stcg((float2*)&g_h2[dir][(t + 1) & 1][d0], make_float2(hnew[0], hnew[1]));
        }
        __syncthreads();

        if (tid == 0) {
            bar_arrive_release(barp);
            unsigned target = 64u * (unsigned)(t + 1);
            while (ld_acquire(barp) < target) { }
        }
        __syncthreads();
    }
}

extern "C" void kernel_launch(void* const* d_in, const int* in_sizes, int n_in,
                              void* d_out, int out_size) {
    const int*   x     = (const int*)d_in[0];
    const float* emb   = (const float*)d_in[1];
    const float* Wih1  = (const float*)d_in[2];
    const float* Whh1  = (const float*)d_in[3];
    const float* bih1  = (const float*)d_in[4];
    const float* bhh1  = (const float*)d_in[5];
    const float* Wih2f = (const float*)d_in[6];
    const float* Whh2f = (const float*)d_in[7];
    const float* bih2f = (const float*)d_in[8];
    const float* bhh2f = (const float*)d_in[9];
    const float* Wih2b = (const float*)d_in[10];
    const float* Whh2b = (const float*)d_in[11];
    const float* bih2b = (const float*)d_in[12];
    const float* bhh2b = (const float*)d_in[13];
    float* out = (float*)d_out;
    float* ctx = out + (size_t)Wn * H1;

    float *p_gi2, *p_b2;
    cudaGetSymbolAddress((void**)&p_gi2, g_gi2);
    cudaGetSymbolAddress((void**)&p_b2,  g_b2);
    __nv_bfloat16 *pAp, *pW1h, *pW1l, *pW2h, *pW2l;
    cudaGetSymbolAddress((void**)&pAp,  g_Ap);
    cudaGetSymbolAddress((void**)&pW1h, g_W1h);
    cudaGetSymbolAddress((void**)&pW1l, g_W1l);
    cudaGetSymbolAddress((void**)&pW2h, g_W2h);
    cudaGetSymbolAddress((void**)&pW2l, g_W2l);
    __nv_bfloat16* buf[2] = { pAp, pAp + (size_t)Wn * KA };

    const int gsmem = 3 * SSTG;   // 107,520 B
    cudaFuncSetAttribute(gemm_fused, cudaFuncAttributeMaxDynamicSharedMemorySize, gsmem);
    cudaFuncSetAttribute(gemm_tail,  cudaFuncAttributeMaxDynamicSharedMemorySize, gsmem);
    dim3 ggf(H1 / 32, Wn / 128);        // (32, 16) fused mainloop
    dim3 ggt(2 * G2 / 96, Wn / 128);    // (64, 16) tail

    convsplit_kernel<<<(G1 * Kd + 255) / 256, 256>>>(Whh1, pW1h, pW1l, nullptr, nullptr);
    table_kernel<<<dim3(G1 / 64, Vn), 256>>>(emb, Wih1, bih1);
    gru1_kernel<<<Wn, 256>>>(x, bhh1, buf[0]);
    for (int t = 1; t < Cn; t++)
        gemm_fused<<<ggf, 256, gsmem>>>(buf[(t + 1) & 1], buf[t & 1], pW1h, pW1l,
                                        x, out, bhh1, t);

    convsplit_kernel<<<(G2 * Kd + 255) / 256, 256>>>(Wih2f, pW2h, pW2l, bih2f, p_b2);
    convsplit_kernel<<<(G2 * Kd + 255) / 256, 256>>>(Wih2b, pW2h + (size_t)G2 * Kd,
                                                     pW2l + (size_t)G2 * Kd, bih2b, p_b2 + G2);
    gemm_tail<<<ggt, 256, gsmem>>>(buf[(Cn - 1) & 1], pW2h, pW2l, p_gi2, p_b2, 2 * G2);

    layer2_kernel<<<128, 256>>>(Whh2f, Whh2b, bhh2f, bhh2b, ctx);
}